// round 8
// baseline (speedup 1.0000x reference)
#include <cuda_runtime.h>
#include <cuda_bf16.h>
#include <cstdint>

// Problem constants
#define T_SEQ 65536
#define F_IN  512
#define H_DIM 64
#define G_DIM 256    // 4*H
#define NT4   (T_SEQ / 4)
#define NSTRIP (T_SEQ / 64)   // 1024 flag strips, 64 timesteps each

typedef unsigned long long ull;

// Scratch (allocation-free rule: __device__ globals)
__device__ __align__(16) float4 g_xgA[(size_t)(NT4 + 2) * 128];
__device__ __align__(16) float4 g_xgB[(size_t)(NT4 + 2) * 128];
__device__ float g_hfin[H_DIM];
__device__ int g_flag[NSTRIP];          // per-strip producer counters (0..4)

// ---------------- packed f32x2 helpers ----------------
static __device__ __forceinline__ ull fma2(ull a, ull b, ull c) {
    ull d;
    asm("fma.rn.f32x2 %0, %1, %2, %3;" : "=l"(d) : "l"(a), "l"(b), "l"(c));
    return d;
}
static __device__ __forceinline__ ull add2(ull a, ull b) {
    ull d;
    asm("add.rn.f32x2 %0, %1, %2;" : "=l"(d) : "l"(a), "l"(b));
    return d;
}
static __device__ __forceinline__ float2 upk(ull a) {
    float2 r;
    asm("mov.b64 {%0, %1}, %2;" : "=f"(r.x), "=f"(r.y) : "l"(a));
    return r;
}
static __device__ __forceinline__ ull pk2(float x, float y) {
    ull r;
    asm("mov.b64 %0, {%1, %2};" : "=l"(r) : "f"(x), "f"(y));
    return r;
}

// ---------------- single-instruction MUFU.TANH ----------------
static __device__ __forceinline__ float tanhap(float x) {
    float r;
    asm("tanh.approx.f32 %0, %1;" : "=f"(r) : "f"(x));
    return r;
}

// Recurrence thread mapping for gate-row r (= g*64 + u)
static __device__ __forceinline__ int map_tid(int g, int u) {
    int odd = g & 1;                 // i,g -> even ; f,o -> odd
    return ((u >> 4) << 5) + ((u & 15) << 1) + odd;
}

// =====================================================================
// Kernel 0: reset strip flags (must run each replay before the fused kernel)
// =====================================================================
__global__ void zero_flags() {
    int i = blockIdx.x * blockDim.x + threadIdx.x;
    if (i < NSTRIP) g_flag[i] = 0;
}

// =====================================================================
// Fused kernel: block 0 = persistent LSTM recurrence (consumer),
// blocks 1..4096 = GEMM tile producers for xg with per-strip flags.
// Producer bid layout: p = bid-1; t-tile = p>>2, colgroup = p&3 so that
// strips complete in t order under bid-ordered scheduling.
// =====================================================================
__global__ void __launch_bounds__(256, 1)
lstm_fused(const float* __restrict__ x,
           const float* __restrict__ Wih,
           const float* __restrict__ bih,
           const float* __restrict__ bhh,
           const float* __restrict__ Whh,
           const float* __restrict__ h0,
           const float* __restrict__ c0) {
    __shared__ float xs[64][17];
    __shared__ float ws[64][17];
    __shared__ __align__(16) float h_sh[2][H_DIM];

    const int tid = threadIdx.x;

    if (blockIdx.x != 0) {
        // ================== PRODUCER: one 64x64 xg tile ==================
        const int p = blockIdx.x - 1;
        const int trow = p >> 2;           // t-tile / strip index
        const int row0 = trow * 64;
        const int col0 = (p & 3) * 64;
        const int tx = tid & 15, ty = tid >> 4;

        float acc[4][4];
#pragma unroll
        for (int i = 0; i < 4; i++)
#pragma unroll
            for (int j = 0; j < 4; j++) acc[i][j] = 0.0f;

        const int l = tid * 4;
        const int lr = l >> 4, lk = l & 15;

        for (int kb = 0; kb < F_IN; kb += 16) {
            float4 xv = *(const float4*)(x + (size_t)(row0 + lr) * F_IN + kb + lk);
            float4 wv = *(const float4*)(Wih + (size_t)(col0 + lr) * F_IN + kb + lk);
            xs[lr][lk] = xv.x; xs[lr][lk + 1] = xv.y; xs[lr][lk + 2] = xv.z; xs[lr][lk + 3] = xv.w;
            ws[lr][lk] = wv.x; ws[lr][lk + 1] = wv.y; ws[lr][lk + 2] = wv.z; ws[lr][lk + 3] = wv.w;
            __syncthreads();
#pragma unroll
            for (int kk = 0; kk < 16; kk++) {
                float a[4], b[4];
#pragma unroll
                for (int i = 0; i < 4; i++) a[i] = xs[ty * 4 + i][kk];
#pragma unroll
                for (int j = 0; j < 4; j++) b[j] = ws[tx * 4 + j][kk];
#pragma unroll
                for (int i = 0; i < 4; i++)
#pragma unroll
                    for (int j = 0; j < 4; j++) acc[i][j] = fmaf(a[i], b[j], acc[i][j]);
            }
            __syncthreads();
        }

        const int tb4 = (row0 + ty * 4) >> 2;
#pragma unroll
        for (int j = 0; j < 4; j++) {
            const int col = col0 + tx * 4 + j;
            const float bj = bih[col] + bhh[col];
            const int gg = col >> 6;            // gate 0=i 1=f 2=g 3=o
            const int uu = col & 63;
            const int pp = map_tid(gg, uu);
            const float sc = (gg == 2) ? 1.0f : 0.5f;  // sigmoid pre-scale (exact)
            float4 o;
            o.x = sc * (acc[0][j] + bj);
            o.y = sc * (acc[1][j] + bj);
            o.z = sc * (acc[2][j] + bj);
            o.w = sc * (acc[3][j] + bj);
            float4* buf = (gg >= 2) ? g_xgB : g_xgA;   // slot B = gates g,o
            buf[(size_t)tb4 * 128 + pp] = o;
        }

        // Publish: all threads fence their stores, then one increments the flag.
        __threadfence();
        __syncthreads();
        if (tid == 0) atomicAdd(&g_flag[trow], 1);
        return;
    }

    // ================== CONSUMER: LSTM recurrence ==================
    // Threads 0..127 compute; 128..255 only participate in barriers.
    const bool active = (tid < 128);
    const int l = tid & 31;
    const int u = ((tid >> 5) << 4) + (l >> 1);   // hidden unit (tid<128)
    const int odd = l & 1;
    const int rA = (odd ? 64 : 0) + u;    // i or f   (sigmoid: pre-scale 0.5)
    const int rB = (odd ? 192 : 128) + u; // g or o   (tanh 1.0 / sigmoid 0.5)
    const float scA = 0.5f;
    const float scB = odd ? 0.5f : 1.0f;

    ull wA[32], wB[32];
    float c = 0.0f, h = 0.0f;
    if (active) {
        const float2* pa = (const float2*)(Whh + (size_t)rA * H_DIM);
        const float2* pb = (const float2*)(Whh + (size_t)rB * H_DIM);
#pragma unroll
        for (int i = 0; i < 32; i++) {
            float2 va = pa[i], vb = pb[i];
            wA[i] = pk2(scA * va.x, scA * va.y);
            wB[i] = pk2(scB * vb.x, scB * vb.y);
        }
        if (odd) c = c0[u];
        if (tid < H_DIM) h_sh[0][tid] = h0[tid];
    }

    const float aB = odd ? 0.5f : 1.0f;
    const float oB = odd ? 0.5f : 0.0f;

    volatile int* vflag = (volatile int*)g_flag;

#define WAIT_STRIP(S) do {                                                    \
        int _s = (S);                                                         \
        if (_s < NSTRIP) {                                                    \
            while (vflag[_s] < 4) { }                                         \
            __threadfence();                                                  \
        }                                                                     \
    } while (0)

#define STEP(XA, XB, RB, WB) do {                                             \
        __syncthreads();                                                      \
        if (active) {                                                         \
            const ulonglong2* hp = (const ulonglong2*)h_sh[RB];               \
            ull a0 = 0, a1 = 0, a2 = 0, a3 = 0;                               \
            ull b0 = 0, b1 = 0, b2 = 0, b3 = 0;                               \
            _Pragma("unroll")                                                 \
            for (int i = 0; i < 8; i++) {                                     \
                ulonglong2 hv = hp[2 * i], hw = hp[2 * i + 1];                \
                a0 = fma2(hv.x, wA[4 * i + 0], a0);                           \
                b0 = fma2(hv.x, wB[4 * i + 0], b0);                           \
                a1 = fma2(hv.y, wA[4 * i + 1], a1);                           \
                b1 = fma2(hv.y, wB[4 * i + 1], b1);                           \
                a2 = fma2(hw.x, wA[4 * i + 2], a2);                           \
                b2 = fma2(hw.x, wB[4 * i + 2], b2);                           \
                a3 = fma2(hw.y, wA[4 * i + 3], a3);                           \
                b3 = fma2(hw.y, wB[4 * i + 3], b3);                           \
            }                                                                 \
            float2 sA = upk(add2(add2(a0, a1), add2(a2, a3)));                \
            float2 sB = upk(add2(add2(b0, b1), add2(b2, b3)));                \
            float preA = (XA) + sA.x + sA.y;                                  \
            float preB = (XB) + sB.x + sB.y;                                  \
            float vA = fmaf(0.5f, tanhap(preA), 0.5f);   /* sigmoid */        \
            float vB = fmaf(aB, tanhap(preB), oB);       /* tanh / sigmoid */ \
            float pr = __shfl_sync(0xffffffffu, vA * vB, l & 30); /* i*g~ */  \
            if (odd) {                                                        \
                c = fmaf(vA, c, pr);           /* c = f*c + i*g~ */           \
                h = vB * tanhap(c);            /* h = o*tanh(c) */            \
                h_sh[WB][u] = h;                                              \
            }                                                                 \
        }                                                                     \
    } while (0)

    // Wait for strip 0, prime the stream, then run.
    WAIT_STRIP(0);
    __syncthreads();   // h_sh[0] visible (matches producers' barrier count? per-CTA only)

    float4 xA0, xB0, xA1, xB1;
    if (active) {
        xA0 = g_xgA[tid];        xB0 = g_xgB[tid];
        xA1 = g_xgA[128 + tid];  xB1 = g_xgB[128 + tid];
    }

    for (int tb = 0; tb < NT4; tb++) {
        // New strip boundary for the prefetch target? Wait before touching it.
        if (((tb + 2) & 15) == 0) WAIT_STRIP((tb + 2) >> 4);
        float4 xA2, xB2;
        if (active) {
            xA2 = g_xgA[(size_t)(tb + 2) * 128 + tid];
            xB2 = g_xgB[(size_t)(tb + 2) * 128 + tid];
        }
        STEP(xA0.x, xB0.x, 0, 1);
        STEP(xA0.y, xB0.y, 1, 0);
        STEP(xA0.z, xB0.z, 0, 1);
        STEP(xA0.w, xB0.w, 1, 0);
        if (active) {
            xA0 = xA1; xA1 = xA2;
            xB0 = xB1; xB1 = xB2;
        }
    }
#undef STEP
#undef WAIT_STRIP

    if (active && odd) g_hfin[u] = h;
}

// =====================================================================
// Kernel 3: out[f] = sigmoid(h_last . W_fc[f] + b_fc[f]),  f < 512
// =====================================================================
__global__ void fc_out(const float* __restrict__ Wfc,
                       const float* __restrict__ bfc,
                       float* __restrict__ out) {
    __shared__ float hsm[H_DIM];
    const int tid = threadIdx.x;   // 0..511
    if (tid < H_DIM) hsm[tid] = g_hfin[tid];
    __syncthreads();
    float acc = bfc[tid];
    const float* wr = Wfc + (size_t)tid * H_DIM;
#pragma unroll
    for (int k = 0; k < H_DIM; k++) acc = fmaf(wr[k], hsm[k], acc);
    out[tid] = 1.0f / (1.0f + __expf(-acc));
}

extern "C" void kernel_launch(void* const* d_in, const int* in_sizes, int n_in,
                              void* d_out, int out_size) {
    const float* x   = (const float*)d_in[0];
    const float* h0  = (const float*)d_in[1];
    const float* c0  = (const float*)d_in[2];
    const float* Wih = (const float*)d_in[3];
    const float* Whh = (const float*)d_in[4];
    const float* bih = (const float*)d_in[5];
    const float* bhh = (const float*)d_in[6];
    const float* Wfc = (const float*)d_in[7];
    const float* bfc = (const float*)d_in[8];
    float* out = (float*)d_out;

    zero_flags<<<(NSTRIP + 255) / 256, 256>>>();
    lstm_fused<<<1 + (T_SEQ / 64) * 4, 256>>>(x, Wih, bih, bhh, Whh, h0, c0);
    fc_out<<<1, 512>>>(Wfc, bfc, out);
}